// round 1
// baseline (speedup 1.0000x reference)
#include <cuda_runtime.h>
#include <math.h>

#define BB   1024
#define NA   32
#define DZ   96
#define DAA  32
#define DD   128
#define NE   8
#define FF   1024
#define HHID 512
#define XP   129   // pad for [32][128] smem tiles
#define WP   132   // pad for [128][128] weight tiles (keeps float4 alignment)

// -------- global scratch (no allocations allowed) --------
__device__ float g_yp[2][BB][NA * DD];   // per-slot expert outputs (33.5 MB)
__device__ int   g_topi[BB][2];
__device__ float g_topg[BB][2];
__device__ float g_lse[BB];

// ============================ helpers ============================

__device__ __forceinline__ void stage_w(float* ws, const float* __restrict__ Wg, int t) {
    // Wg: [128 rows m][128 cols d] row-major -> ws[d*WP + m] (transposed)
    for (int i = t; i < 128 * 128; i += 256) {
        int m = i >> 7, d = i & 127;
        ws[d * WP + m] = Wg[i];
    }
}

// out[na0..na0+1][m0..m0+7] += X[32][128](smem,XP) @ W^T staged as ws[d][m]
__device__ __forceinline__ void mm_tile(const float* __restrict__ xsm,
                                        const float* __restrict__ wsm,
                                        int na0, int m0, float acc[16]) {
    const float* xr0 = xsm + na0 * XP;
    const float* xr1 = xr0 + XP;
    const float* wr  = wsm + m0;
#pragma unroll 4
    for (int d = 0; d < 128; d++) {
        float4 wa = *reinterpret_cast<const float4*>(wr);
        float4 wb = *reinterpret_cast<const float4*>(wr + 4);
        wr += WP;
        float x0 = xr0[d], x1 = xr1[d];
        acc[0]  += x0 * wa.x; acc[1]  += x0 * wa.y; acc[2]  += x0 * wa.z; acc[3]  += x0 * wa.w;
        acc[4]  += x0 * wb.x; acc[5]  += x0 * wb.y; acc[6]  += x0 * wb.z; acc[7]  += x0 * wb.w;
        acc[8]  += x1 * wa.x; acc[9]  += x1 * wa.y; acc[10] += x1 * wa.z; acc[11] += x1 * wa.w;
        acc[12] += x1 * wb.x; acc[13] += x1 * wb.y; acc[14] += x1 * wb.z; acc[15] += x1 * wb.w;
    }
}

__device__ __forceinline__ float warp_sum(float s) {
#pragma unroll
    for (int off = 16; off; off >>= 1) s += __shfl_xor_sync(0xffffffffu, s, off);
    return s;
}

// in-place layernorm over rows of buf[32][XP] (D=128), 8 warps / 32 rows
__device__ __forceinline__ void block_ln(float* buf, const float* __restrict__ g,
                                         const float* __restrict__ bt, int t) {
    int w = t >> 5, lane = t & 31;
    for (int row = w; row < 32; row += 8) {
        float* base = buf + row * XP;
        float v0 = base[lane], v1 = base[lane + 32], v2 = base[lane + 64], v3 = base[lane + 96];
        float mu = warp_sum(v0 + v1 + v2 + v3) * (1.f / 128.f);
        float d0 = v0 - mu, d1 = v1 - mu, d2 = v2 - mu, d3 = v3 - mu;
        float var = warp_sum(d0 * d0 + d1 * d1 + d2 * d2 + d3 * d3) * (1.f / 128.f);
        float rs = rsqrtf(var + 1e-5f);
        base[lane]      = d0 * rs * g[lane]      + bt[lane];
        base[lane + 32] = d1 * rs * g[lane + 32] + bt[lane + 32];
        base[lane + 64] = d2 * rs * g[lane + 64] + bt[lane + 64];
        base[lane + 96] = d3 * rs * g[lane + 96] + bt[lane + 96];
    }
}

// ============================ router ============================

__global__ void __launch_bounds__(256) router_kernel(const float* __restrict__ z,
                                                     const float* __restrict__ a,
                                                     const float* __restrict__ wg,
                                                     float* __restrict__ gates_out) {
    int b = blockIdx.x, t = threadIdx.x;
    float acc[8];
#pragma unroll
    for (int e = 0; e < 8; e++) acc[e] = 0.f;

    for (int i = t; i < NA * DD; i += 256) {
        int na = i >> 7, d = i & 127;
        float xv = (d < DZ) ? z[(b * NA + na) * DZ + d] : a[(b * NA + na) * DAA + (d - DZ)];
        const float4* wr = reinterpret_cast<const float4*>(wg + (size_t)i * 8);
        float4 w0 = wr[0], w1 = wr[1];
        acc[0] += xv * w0.x; acc[1] += xv * w0.y; acc[2] += xv * w0.z; acc[3] += xv * w0.w;
        acc[4] += xv * w1.x; acc[5] += xv * w1.y; acc[6] += xv * w1.z; acc[7] += xv * w1.w;
    }

    __shared__ float sred[8 * 8];
    __shared__ float lgs[8];
    int w = t >> 5, lane = t & 31;
#pragma unroll
    for (int e = 0; e < 8; e++) {
        float s = warp_sum(acc[e]);
        if (lane == 0) sred[w * 8 + e] = s;
    }
    __syncthreads();
    if (t < 8) {
        float s = 0.f;
#pragma unroll
        for (int ww = 0; ww < 8; ww++) s += sred[ww * 8 + t];
        lgs[t] = s;
    }
    __syncthreads();
    if (t == 0) {
        float m = lgs[0];
#pragma unroll
        for (int e = 1; e < 8; e++) m = fmaxf(m, lgs[e]);
        float se = 0.f;
#pragma unroll
        for (int e = 0; e < 8; e++) se += expf(lgs[e] - m);
        g_lse[b] = logf(se) + m;

        int i0 = 0; float v0 = lgs[0];
#pragma unroll
        for (int e = 1; e < 8; e++) if (lgs[e] > v0) { v0 = lgs[e]; i0 = e; }
        int i1 = -1; float v1 = -1e30f;
#pragma unroll
        for (int e = 0; e < 8; e++) if (e != i0 && lgs[e] > v1) { v1 = lgs[e]; i1 = e; }

        float ex = expf(v1 - v0);
        float inv = 1.f / (1.f + ex);
        float g0 = inv, g1 = ex * inv;
#pragma unroll
        for (int e = 0; e < 8; e++) gates_out[b * 8 + e] = 0.f;
        gates_out[b * 8 + i0] = g0;
        gates_out[b * 8 + i1] = g1;
        g_topi[b][0] = i0; g_topi[b][1] = i1;
        g_topg[b][0] = g0; g_topg[b][1] = g1;
    }
}

// ============================ expert ============================
// smem float offsets
#define O_XS 0
#define O_WS 4128
#define O_QS 21024
#define O_KS 25152
#define O_VS 29280
#define O_HS 33408
#define O_FS 37536
#define EXPERT_SMEM_FLOATS 41664
#define EXPERT_SMEM_BYTES  (EXPERT_SMEM_FLOATS * 4)

__global__ void __launch_bounds__(256) expert_kernel(
    const float* __restrict__ z,    const float* __restrict__ a,
    const float* __restrict__ w_in, const float* __restrict__ b_in,
    const float* __restrict__ w_out,const float* __restrict__ b_out,
    const float* __restrict__ ln1g, const float* __restrict__ ln1b,
    const float* __restrict__ w1,   const float* __restrict__ b1,
    const float* __restrict__ w2,   const float* __restrict__ b2,
    const float* __restrict__ ln2g, const float* __restrict__ ln2b) {
    extern __shared__ float sm[];
    float* xs = sm + O_XS;
    float* ws = sm + O_WS;
    float* qs = sm + O_QS;
    float* ks = sm + O_KS;
    float* vs = sm + O_VS;
    float* hs = sm + O_HS;
    float* fs = sm + O_FS;

    int t = threadIdx.x;
    int bid = blockIdx.x;
    int b = bid >> 1, s = bid & 1;
    int e = g_topi[b][s];
    float gate = g_topg[b][s];
    int tx = t & 15, ty = t >> 4;
    int m0 = tx * 8, na0 = ty * 2;

    // ---- load x = concat(z, a) ----
    for (int i = t; i < NA * DD; i += 256) {
        int na = i >> 7, d = i & 127;
        float xv = (d < DZ) ? z[(b * NA + na) * DZ + d] : a[(b * NA + na) * DAA + (d - DZ)];
        xs[na * XP + d] = xv;
    }
    __syncthreads();

    // ---- qkv = x @ wi^T + bi ----
    const float* wi = w_in + (size_t)e * 384 * 128;
    const float* bi = b_in + (size_t)e * 384;
    float* outs[3] = {qs, ks, vs};
#pragma unroll
    for (int tile = 0; tile < 3; tile++) {
        stage_w(ws, wi + tile * 128 * 128, t);
        __syncthreads();
        float acc[16];
#pragma unroll
        for (int i = 0; i < 16; i++) acc[i] = 0.f;
        mm_tile(xs, ws, na0, m0, acc);
#pragma unroll
        for (int r = 0; r < 2; r++)
#pragma unroll
            for (int c = 0; c < 8; c++)
                outs[tile][(na0 + r) * XP + m0 + c] = acc[r * 8 + c] + bi[tile * 128 + m0 + c];
        __syncthreads();
    }

    // ---- attention scores (4 heads x 32 x 32) -> fs ----
    const float scale = 0.17677669529663687f;  // 1/sqrt(32)
    for (int i = t; i < 4096; i += 256) {
        int h = i >> 10, qi = (i >> 5) & 31, kj = i & 31;
        const float* qp = qs + qi * XP + h * 32;
        const float* kp = ks + kj * XP + h * 32;
        float acc = 0.f;
#pragma unroll
        for (int d = 0; d < 32; d++) acc += qp[d] * kp[d];
        fs[i] = acc * scale;
    }
    __syncthreads();
    // ---- softmax rows ----
    if (t < 128) {
        float* row = fs + t * 32;
        float m = row[0];
#pragma unroll
        for (int j = 1; j < 32; j++) m = fmaxf(m, row[j]);
        float ssum = 0.f;
#pragma unroll
        for (int j = 0; j < 32; j++) { float ee = expf(row[j] - m); row[j] = ee; ssum += ee; }
        float inv = 1.f / ssum;
#pragma unroll
        for (int j = 0; j < 32; j++) row[j] *= inv;
    }
    __syncthreads();
    // ---- o = att @ v  (overwrite qs) ----
    for (int i = t; i < 4096; i += 256) {
        int na = i >> 7, c = i & 127, h = c >> 5, j = c & 31;
        const float* ap = fs + (h * 32 + na) * 32;
        float acc = 0.f;
#pragma unroll
        for (int k = 0; k < 32; k++) acc += ap[k] * vs[k * XP + h * 32 + j];
        qs[na * XP + c] = acc;
    }
    __syncthreads();

    // ---- o-proj + residual -> hs ----
    stage_w(ws, w_out + (size_t)e * 128 * 128, t);
    __syncthreads();
    {
        float acc[16];
#pragma unroll
        for (int i = 0; i < 16; i++) acc[i] = 0.f;
        mm_tile(qs, ws, na0, m0, acc);
        const float* bo = b_out + (size_t)e * 128;
#pragma unroll
        for (int r = 0; r < 2; r++)
#pragma unroll
            for (int c = 0; c < 8; c++)
                hs[(na0 + r) * XP + m0 + c] =
                    acc[r * 8 + c] + bo[m0 + c] + xs[(na0 + r) * XP + m0 + c];
    }
    __syncthreads();

    // ---- LN1 ----
    block_ln(hs, ln1g + (size_t)e * 128, ln1b + (size_t)e * 128, t);
    __syncthreads();

    // ---- FFN ----
    const float* W1 = w1 + (size_t)e * FF * DD;
    const float* B1 = b1 + (size_t)e * FF;
    const float* W2 = w2 + (size_t)e * DD * FF;
    const float* B2 = b2 + (size_t)e * DD;
    float facc[16];
#pragma unroll
    for (int i = 0; i < 16; i++) facc[i] = 0.f;

    for (int ft = 0; ft < 8; ft++) {
        stage_w(ws, W1 + ft * 128 * 128, t);
        __syncthreads();
        float tacc[16];
#pragma unroll
        for (int i = 0; i < 16; i++) tacc[i] = 0.f;
        mm_tile(hs, ws, na0, m0, tacc);
#pragma unroll
        for (int r = 0; r < 2; r++)
#pragma unroll
            for (int c = 0; c < 8; c++) {
                float v = tacc[r * 8 + c] + B1[ft * 128 + m0 + c];
                fs[(na0 + r) * XP + m0 + c] = fmaxf(v, 0.f);
            }
        __syncthreads();
        // stage W2 tile transposed: ws[f*WP + d] = W2[d][ft*128 + f]
        for (int i = t; i < 128 * 128; i += 256) {
            int d = i >> 7, f = i & 127;
            ws[f * WP + d] = W2[(size_t)d * FF + ft * 128 + f];
        }
        __syncthreads();
        mm_tile(fs, ws, na0, m0, facc);
        __syncthreads();
    }

    // ---- epilogue: +bias +residual -> fs ----
#pragma unroll
    for (int r = 0; r < 2; r++)
#pragma unroll
        for (int c = 0; c < 8; c++)
            fs[(na0 + r) * XP + m0 + c] =
                facc[r * 8 + c] + B2[m0 + c] + hs[(na0 + r) * XP + m0 + c];
    __syncthreads();

    // ---- LN2, scale by gate, write to per-slot scratch ----
    {
        int w = t >> 5, lane = t & 31;
        const float* g2  = ln2g + (size_t)e * 128;
        const float* be2 = ln2b + (size_t)e * 128;
        for (int row = w; row < 32; row += 8) {
            float* base = fs + row * XP;
            float v0 = base[lane], v1 = base[lane + 32], v2 = base[lane + 64], v3 = base[lane + 96];
            float mu = warp_sum(v0 + v1 + v2 + v3) * (1.f / 128.f);
            float d0 = v0 - mu, d1 = v1 - mu, d2 = v2 - mu, d3 = v3 - mu;
            float var = warp_sum(d0 * d0 + d1 * d1 + d2 * d2 + d3 * d3) * (1.f / 128.f);
            float rs = rsqrtf(var + 1e-5f);
            float* outp = &g_yp[s][b][row * 128];
            outp[lane]      = (d0 * rs * g2[lane]      + be2[lane])      * gate;
            outp[lane + 32] = (d1 * rs * g2[lane + 32] + be2[lane + 32]) * gate;
            outp[lane + 64] = (d2 * rs * g2[lane + 64] + be2[lane + 64]) * gate;
            outp[lane + 96] = (d3 * rs * g2[lane + 96] + be2[lane + 96]) * gate;
        }
    }
}

// ============================ head ============================
#define HO_YS  0
#define HO_W1  2112
#define HO_H2  19008
#define HEAD_SMEM_FLOATS 27264
#define HEAD_SMEM_BYTES  (HEAD_SMEM_FLOATS * 4)

__global__ void __launch_bounds__(256) head_kernel(const float* __restrict__ hw1,
                                                   const float* __restrict__ hb1,
                                                   const float* __restrict__ hw2,
                                                   const float* __restrict__ hb2,
                                                   float* __restrict__ r_out) {
    extern __shared__ float sm[];
    float* ys  = sm + HO_YS;   // [16][WP]
    float* w1s = sm + HO_W1;   // [128][WP]
    float* h2  = sm + HO_H2;   // [16][516]
    int t = threadIdx.x;
    int bt = blockIdx.x;            // 16 tokens each
    int tx = t & 15, ty = t >> 4;
    int h0 = tx * 8;

    for (int ht = 0; ht < 4; ht++) {
        float acc[8];
#pragma unroll
        for (int c = 0; c < 8; c++) acc[c] = 0.f;
        for (int kt = 0; kt < 32; kt++) {
            for (int i = t; i < 16 * 128; i += 256) {
                int tok = i >> 7, d = i & 127;
                int bidx = bt * 16 + tok, col = kt * 128 + d;
                ys[tok * WP + d] = g_yp[0][bidx][col] + g_yp[1][bidx][col];
            }
            for (int i = t; i < 128 * 128; i += 256) {
                int m = i >> 7, d = i & 127;
                w1s[d * WP + m] = hw1[(size_t)(ht * 128 + m) * 4096 + kt * 128 + d];
            }
            __syncthreads();
            const float* xr = ys + ty * WP;
            const float* wr = w1s + h0;
#pragma unroll 4
            for (int d = 0; d < 128; d++) {
                float4 wa = *reinterpret_cast<const float4*>(wr);
                float4 wb = *reinterpret_cast<const float4*>(wr + 4);
                wr += WP;
                float xv = xr[d];
                acc[0] += xv * wa.x; acc[1] += xv * wa.y; acc[2] += xv * wa.z; acc[3] += xv * wa.w;
                acc[4] += xv * wb.x; acc[5] += xv * wb.y; acc[6] += xv * wb.z; acc[7] += xv * wb.w;
            }
            __syncthreads();
        }
#pragma unroll
        for (int c = 0; c < 8; c++) {
            int hh = ht * 128 + h0 + c;
            h2[ty * 516 + hh] = fmaxf(acc[c] + hb1[hh], 0.f);
        }
    }
    __syncthreads();
    if (t < 64) {
        int tok = t >> 2, o = t & 3;
        const float* hp = h2 + tok * 516;
        const float* wp = hw2 + (size_t)o * 512;
        float acc = 0.f;
        for (int j = 0; j < 512; j++) acc += hp[j] * wp[j];
        r_out[(bt * 16 + tok) * 4 + o] = acc + hb2[o];
    }
}

// ============================ loss ============================

__global__ void __launch_bounds__(256) loss_kernel(const float* __restrict__ gates,
                                                   float* __restrict__ loss_out) {
    int t = threadIdx.x;
    float imp[8], ld[8];
#pragma unroll
    for (int e = 0; e < 8; e++) { imp[e] = 0.f; ld[e] = 0.f; }
    float lsum = 0.f;
    for (int b = t; b < BB; b += 256) {
#pragma unroll
        for (int e = 0; e < 8; e++) {
            float g = gates[b * 8 + e];
            imp[e] += g;
            ld[e]  += (g > 0.f) ? 1.f : 0.f;
        }
        lsum += g_lse[b];
    }
    __shared__ float simp[8 * 8], sld[8 * 8], sls[8];
    int w = t >> 5, lane = t & 31;
#pragma unroll
    for (int e = 0; e < 8; e++) {
        float si = warp_sum(imp[e]);
        float sl = warp_sum(ld[e]);
        if (lane == 0) { simp[w * 8 + e] = si; sld[w * 8 + e] = sl; }
    }
    {
        float sl2 = warp_sum(lsum);
        if (lane == 0) sls[w] = sl2;
    }
    __syncthreads();
    if (t == 0) {
        float I[8], L[8];
        float ls = 0.f;
#pragma unroll
        for (int ww = 0; ww < 8; ww++) ls += sls[ww];
#pragma unroll
        for (int e = 0; e < 8; e++) {
            float si = 0.f, sl = 0.f;
#pragma unroll
            for (int ww = 0; ww < 8; ww++) { si += simp[ww * 8 + e]; sl += sld[ww * 8 + e]; }
            I[e] = si; L[e] = sl;
        }
        float mi = 0.f, ml = 0.f;
#pragma unroll
        for (int e = 0; e < 8; e++) { mi += I[e]; ml += L[e]; }
        mi *= (1.f / 8.f); ml *= (1.f / 8.f);
        float vi = 0.f, vl = 0.f;
#pragma unroll
        for (int e = 0; e < 8; e++) {
            vi += (I[e] - mi) * (I[e] - mi);
            vl += (L[e] - ml) * (L[e] - ml);
        }
        vi *= (1.f / 7.f); vl *= (1.f / 7.f);
        float cv2i = vi / (mi * mi + 1e-10f);
        float cv2l = vl / (ml * ml + 1e-10f);
        loss_out[0] = cv2i + cv2l + ls * (1.f / (float)BB);
    }
}

// ============================ launch ============================

extern "C" void kernel_launch(void* const* d_in, const int* in_sizes, int n_in,
                              void* d_out, int out_size) {
    const float* z      = (const float*)d_in[0];
    const float* a      = (const float*)d_in[1];
    const float* w_gate = (const float*)d_in[2];
    const float* w_in   = (const float*)d_in[3];
    const float* b_in   = (const float*)d_in[4];
    const float* w_out  = (const float*)d_in[5];
    const float* b_out  = (const float*)d_in[6];
    const float* ln1_g  = (const float*)d_in[7];
    const float* ln1_b  = (const float*)d_in[8];
    const float* w1     = (const float*)d_in[9];
    const float* b1     = (const float*)d_in[10];
    const float* w2     = (const float*)d_in[11];
    const float* b2     = (const float*)d_in[12];
    const float* ln2_g  = (const float*)d_in[13];
    const float* ln2_b  = (const float*)d_in[14];
    const float* hw1    = (const float*)d_in[15];
    const float* hb1    = (const float*)d_in[16];
    const float* hw2    = (const float*)d_in[17];
    const float* hb2    = (const float*)d_in[18];

    float* out       = (float*)d_out;
    float* r_out     = out;                 // [1024,4]
    float* gates_out = out + BB * 4;        // [1024,8]
    float* loss_out  = out + BB * 4 + BB * 8;  // scalar

    cudaFuncSetAttribute(expert_kernel, cudaFuncAttributeMaxDynamicSharedMemorySize,
                         EXPERT_SMEM_BYTES);
    cudaFuncSetAttribute(head_kernel, cudaFuncAttributeMaxDynamicSharedMemorySize,
                         HEAD_SMEM_BYTES);

    router_kernel<<<BB, 256>>>(z, a, w_gate, gates_out);
    expert_kernel<<<BB * 2, 256, EXPERT_SMEM_BYTES>>>(z, a, w_in, b_in, w_out, b_out,
                                                      ln1_g, ln1_b, w1, b1, w2, b2,
                                                      ln2_g, ln2_b);
    head_kernel<<<BB / 16, 256, HEAD_SMEM_BYTES>>>(hw1, hb1, hw2, hb2, r_out);
    loss_kernel<<<1, 256>>>(gates_out, loss_out);
}